// round 11
// baseline (speedup 1.0000x reference)
#include <cuda_runtime.h>

// Fused masked-scale MSE, round 11:
//   Mainloop = R8 verbatim (v8 256-bit loads, grid 2048x256, predicated
//   grid-stride — co-best measured; mainloop is converged at the DRAM
//   plateau, ncu kernel times showed ±1.5us run noise on identical bins).
//   ONE change, in the epilogue: block partials spread across 64 atomic
//   slots padded to 128B (B300: same-address L2 atomics serialize ~0.854
//   cyc/op -> 2048-deep chain ~0.9us on the ticket's critical path;
//   >=128B-strided distinct addresses are ~63x faster). Last block sums
//   the 64 slots, writes out, resets state for graph replay.

constexpr int SLOTS = 64;
constexpr int SLOT_STRIDE = 32;   // 32 floats = 128 B between slot addresses

__device__ float        g_partials[SLOTS * SLOT_STRIDE];  // zero-initialized
__device__ unsigned int g_ticket = 0u;

struct f8 { float a, b, c, d, e, f, g, h; };

__device__ __forceinline__ f8 ldg256(const float* __restrict__ p) {
    f8 v;
    asm("ld.global.v8.f32 {%0,%1,%2,%3,%4,%5,%6,%7}, [%8];"
        : "=f"(v.a), "=f"(v.b), "=f"(v.c), "=f"(v.d),
          "=f"(v.e), "=f"(v.f), "=f"(v.g), "=f"(v.h)
        : "l"(p));
    return v;
}

__device__ __forceinline__ float elem_term(float n, float l) {
    // labels are exactly 0.0f, 1.0f, or 2.0f
    float sn = (l == 1.0f) ? 10.0f : ((l == 2.0f) ? 5.0f : 1.0f);
    float sl = (l == 0.0f) ? 1.0f : 10.0f;
    float d = fmaf(n, sn, -l * sl);
    return d * d;
}

__global__ void __launch_bounds__(256)
mse_loss_kernel(const float* __restrict__ norms,
                const float* __restrict__ labels,
                float* __restrict__ out,
                int n_vec8,     // number of 8-float groups
                float inv_n)
{
    int idx = blockIdx.x * blockDim.x + threadIdx.x;
    int stride = gridDim.x * blockDim.x;

    float acc = 0.0f;
    // One iteration = 2 x 256-bit loads = 16 floats in flight. (R8 mainloop.)
    for (int i = idx; i < n_vec8; i += stride) {
        f8 a = ldg256(norms  + (size_t)i * 8);
        f8 b = ldg256(labels + (size_t)i * 8);
        acc += elem_term(a.a, b.a);
        acc += elem_term(a.b, b.b);
        acc += elem_term(a.c, b.c);
        acc += elem_term(a.d, b.d);
        acc += elem_term(a.e, b.e);
        acc += elem_term(a.f, b.f);
        acc += elem_term(a.g, b.g);
        acc += elem_term(a.h, b.h);
    }

    // warp reduction
    #pragma unroll
    for (int off = 16; off > 0; off >>= 1)
        acc += __shfl_down_sync(0xffffffffu, acc, off);

    __shared__ float warp_sums[8];
    int lane = threadIdx.x & 31;
    int wid  = threadIdx.x >> 5;
    if (lane == 0) warp_sums[wid] = acc;
    __syncthreads();

    if (wid == 0) {
        float v = (lane < (int)(blockDim.x >> 5)) ? warp_sums[lane] : 0.0f;
        #pragma unroll
        for (int off = 4; off > 0; off >>= 1)
            v += __shfl_down_sync(0xffffffffu, v, off);

        if (lane == 0) {
            // Spread contention: 64 slot addresses, 128B apart.
            int slot = (blockIdx.x & (SLOTS - 1)) * SLOT_STRIDE;
            atomicAdd(&g_partials[slot], v);
            __threadfence();
            unsigned int ticket = atomicAdd(&g_ticket, 1u);
            if (ticket == gridDim.x - 1) {
                // all partials visible; sum slots, finish, reset for replay
                float total = 0.0f;
                #pragma unroll
                for (int s = 0; s < SLOTS; s++) {
                    total += g_partials[s * SLOT_STRIDE];
                    g_partials[s * SLOT_STRIDE] = 0.0f;
                }
                out[0] = total * inv_n;
                g_ticket = 0u;
            }
        }
    }
}

extern "C" void kernel_launch(void* const* d_in, const int* in_sizes, int n_in,
                              void* d_out, int out_size)
{
    const float* norms  = (const float*)d_in[0];
    const float* labels = (const float*)d_in[1];
    float* out = (float*)d_out;

    int n_elems = in_sizes[0];        // 33554432
    int n_vec8  = n_elems / 8;        // 4194304 (exact)
    float inv_n = 1.0f / (float)n_elems;

    const int threads = 256;
    const int blocks  = 2048;         // measured-best grid point

    mse_loss_kernel<<<blocks, threads>>>(norms, labels, out, n_vec8, inv_n);
}

// round 12
// speedup vs baseline: 1.0449x; 1.0449x over previous
#include <cuda_runtime.h>

// Fused masked-scale MSE — FINAL (= R5, best recorded total 43.23us).
//
// Converged evidence across 11 rounds:
//  - mainloop: predicated 2x-unroll grid-stride float4 == v8-256bit (within
//    noise); pointer-carried/counted loops lost 3x; __ldcs lost.
//  - indexing: int32 > long long (alu 26% vs 34%).
//  - grid: 1216 < 2048 > 4096 (2048 x 256thr best).
//  - epilogue: single-address atomicAdd + last-block ticket beats both a
//    separate zero-init launch (-1.3us) and 64-slot spread atomics (R11 regr).
//  - roofline: 6.4-6.6 TB/s plateau == B300 LTS structural cap; MLP saturated
//    14x over latency-hiding requirement. At the ceiling.

__device__ float        g_partial = 0.0f;
__device__ unsigned int g_ticket  = 0u;

__device__ __forceinline__ float elem_term(float n, float l) {
    // labels are exactly 0.0f, 1.0f, or 2.0f
    float sn = (l == 1.0f) ? 10.0f : ((l == 2.0f) ? 5.0f : 1.0f);
    float sl = (l == 0.0f) ? 1.0f : 10.0f;
    float d = fmaf(n, sn, -l * sl);
    return d * d;
}

__global__ void __launch_bounds__(256)
mse_loss_kernel(const float* __restrict__ norms,
                const float* __restrict__ labels,
                float* __restrict__ out,
                int n_vec,      // number of float4 elements
                float inv_n)
{
    const float4* __restrict__ n4 = reinterpret_cast<const float4*>(norms);
    const float4* __restrict__ l4 = reinterpret_cast<const float4*>(labels);

    int idx = blockIdx.x * blockDim.x + threadIdx.x;
    int stride = gridDim.x * blockDim.x;

    float acc = 0.0f;
    // 2x unroll of the grid-stride loop: front-batches 4 float4 loads
    // per iteration for high MLP.  (Measured-best mainloop shape.)
    for (int i = idx; i < n_vec; i += 2 * stride) {
        float4 a0 = n4[i];
        float4 b0 = l4[i];
        int j = i + stride;
        float4 a1, b1;
        bool have2 = (j < n_vec);
        if (have2) { a1 = n4[j]; b1 = l4[j]; }

        acc += elem_term(a0.x, b0.x);
        acc += elem_term(a0.y, b0.y);
        acc += elem_term(a0.z, b0.z);
        acc += elem_term(a0.w, b0.w);
        if (have2) {
            acc += elem_term(a1.x, b1.x);
            acc += elem_term(a1.y, b1.y);
            acc += elem_term(a1.z, b1.z);
            acc += elem_term(a1.w, b1.w);
        }
    }

    // warp reduction
    #pragma unroll
    for (int off = 16; off > 0; off >>= 1)
        acc += __shfl_down_sync(0xffffffffu, acc, off);

    __shared__ float warp_sums[8];
    int lane = threadIdx.x & 31;
    int wid  = threadIdx.x >> 5;
    if (lane == 0) warp_sums[wid] = acc;
    __syncthreads();

    if (wid == 0) {
        float v = (lane < (int)(blockDim.x >> 5)) ? warp_sums[lane] : 0.0f;
        #pragma unroll
        for (int off = 4; off > 0; off >>= 1)
            v += __shfl_down_sync(0xffffffffu, v, off);

        if (lane == 0) {
            atomicAdd(&g_partial, v);
            __threadfence();
            unsigned int ticket = atomicAdd(&g_ticket, 1u);
            if (ticket == gridDim.x - 1) {
                // all block partials visible; finish and reset for next replay
                out[0] = g_partial * inv_n;
                g_partial = 0.0f;
                g_ticket  = 0u;
            }
        }
    }
}

extern "C" void kernel_launch(void* const* d_in, const int* in_sizes, int n_in,
                              void* d_out, int out_size)
{
    const float* norms  = (const float*)d_in[0];
    const float* labels = (const float*)d_in[1];
    float* out = (float*)d_out;

    int n_elems = in_sizes[0];        // 33554432
    int n_vec   = n_elems / 4;        // 8388608
    float inv_n = 1.0f / (float)n_elems;

    const int threads = 256;
    const int blocks  = 2048;

    mse_loss_kernel<<<blocks, threads>>>(norms, labels, out, n_vec, inv_n);
}